// round 3
// baseline (speedup 1.0000x reference)
#include <cuda_runtime.h>
#include <cuda_fp16.h>
#include <math.h>

#define NN 100000
#define EE 1600000
#define MM (EE + NN)
#define NB 49            // ceil(NN / 2048)
#define EPSV 1e-5f

// ---------------- scratch (static device allocations; no cudaMalloc) ----------------
__device__ int    g_is64;
__device__ int    g_deg[NN];
__device__ float  g_dinv[NN];
__device__ int    g_start[NN];
__device__ int    g_cursor[NN];
__device__ int    g_tilesum[NB];
__device__ int    g_tileoff[NB];
__device__ int2   g_cw[MM];          // (src, norm-bits) per CSR slot
__device__ float  g_s[NN];           // row sums of normalized adjacency
__device__ __half2 g_h[NN * 32];     // GEMM output, fp16, row stride 32 half2 (128B)
__device__ float  g_agg[NN * 64];    // aggregation output (fp32)
__device__ float  g_stats1[128];     // [sum(64), sumsq(64)]
__device__ float  g_stats2[128];
__device__ float  g_W2f[64 * 64];    // BN1-folded W2
__device__ float  g_W3f[64 * 40];    // BN2-folded W3
__device__ float  g_t2[64];
__device__ float  g_t3[64];
__device__ float  g_zero64[64];

// ---------------- graph build ----------------
__global__ void k_init() {
    int i = blockIdx.x * blockDim.x + threadIdx.x;
    if (i < NN) { g_deg[i] = 1; g_s[i] = 0.f; }      // self-loop
    if (i < 128) { g_stats1[i] = 0.f; g_stats2[i] = 0.f; }
    if (i < 64) g_zero64[i] = 0.f;
    if (i == 0) g_is64 = 1;
}

// Sampled dtype detect: if buffer is int64, sampled entries are edge_index[0]
// values in [0, NN). If int32, a 64-bit reinterpretation has its high word =
// the next int32 index (nonzero w.p. 1-1e-5) -> out of range -> flag flips.
__global__ void k_detect(const long long* __restrict__ p) {
    int i = blockIdx.x * blockDim.x + threadIdx.x;   // 65536 threads
    long long v = p[(size_t)i * 24];                 // stays < EE int64 slots
    if (v < 0 || v >= NN) g_is64 = 0;                // benign race: all store 0
}

__device__ __forceinline__ long long edge_at(const void* ei, int idx) {
    if (g_is64) return ((const long long*)ei)[idx];
    return (long long)((const int*)ei)[idx];
}

__global__ void k_degree(const void* __restrict__ ei) {
    int i = blockIdx.x * blockDim.x + threadIdx.x;
    if (i >= EE) return;
    long long d = edge_at(ei, EE + i);
    if ((unsigned long long)d < (unsigned long long)NN)
        atomicAdd(&g_deg[(int)d], 1);
}

__global__ void k_dinv() {
    int i = blockIdx.x * blockDim.x + threadIdx.x;
    if (i < NN) g_dinv[i] = rsqrtf((float)g_deg[i]);
}

__global__ void k_scanA() {   // block-tile sums (tile = 2048)
    int base = blockIdx.x * 2048;
    int s = 0;
    for (int i = threadIdx.x; i < 2048; i += 256) {
        int idx = base + i;
        if (idx < NN) s += g_deg[idx];
    }
    __shared__ int sh[256];
    sh[threadIdx.x] = s;
    __syncthreads();
    for (int o = 128; o > 0; o >>= 1) {
        if (threadIdx.x < o) sh[threadIdx.x] += sh[threadIdx.x + o];
        __syncthreads();
    }
    if (threadIdx.x == 0) g_tilesum[blockIdx.x] = sh[0];
}

__global__ void k_scanB() {   // exclusive scan of NB tile sums
    if (threadIdx.x == 0) {
        int a = 0;
        for (int b = 0; b < NB; b++) { g_tileoff[b] = a; a += g_tilesum[b]; }
    }
}

__global__ void k_scanC() {   // intra-tile exclusive scan -> start/cursor
    int tid = threadIdx.x;
    int base = blockIdx.x * 2048 + tid * 8;
    int loc[8];
    int s = 0;
    #pragma unroll
    for (int j = 0; j < 8; j++) {
        int idx = base + j;
        int d = (idx < NN) ? g_deg[idx] : 0;
        loc[j] = s; s += d;
    }
    __shared__ int sh[256];
    sh[tid] = s;
    __syncthreads();
    int run = s;
    for (int o = 1; o < 256; o <<= 1) {
        int v = (tid >= o) ? sh[tid - o] : 0;
        __syncthreads();
        sh[tid] += v;
        __syncthreads();
    }
    int off = g_tileoff[blockIdx.x] + sh[tid] - run;
    #pragma unroll
    for (int j = 0; j < 8; j++) {
        int idx = base + j;
        if (idx < NN) { int p = off + loc[j]; g_start[idx] = p; g_cursor[idx] = p; }
    }
}

// CSR fill + fused row-sum (s_d accumulated via float atomics).
__global__ void k_fill(const void* __restrict__ ei) {
    int i = blockIdx.x * blockDim.x + threadIdx.x;
    if (i >= MM) return;
    int s, d;
    if (i < EE) {
        long long ls = edge_at(ei, i);
        long long ld = edge_at(ei, EE + i);
        if ((unsigned long long)ls >= (unsigned long long)NN) return;
        if ((unsigned long long)ld >= (unsigned long long)NN) return;
        s = (int)ls; d = (int)ld;
    } else {
        s = i - EE; d = s;
    }
    float w = g_dinv[s] * g_dinv[d];
    int pos = atomicAdd(&g_cursor[d], 1);
    g_cw[pos] = make_int2(s, __float_as_int(w));
    atomicAdd(&g_s[d], w);
}

// ---------------- GEMM: out[N x NC](fp16, row stride OS halves) = in[N x 64] @ W[64 x NC]
// blockDim must be (NC/4)*16; block tile = 64 rows x NC cols.
template <int NC, int OS>
__global__ void k_gemm(const float* __restrict__ in, const float* __restrict__ W,
                       __half* __restrict__ out) {
    __shared__ float XsT[64 * 68];   // [k][row], padded
    __shared__ float Ws[64 * NC];    // [k][j]
    const int nth = (NC / 4) * 16;
    int tid = threadIdx.x;
    int row0 = blockIdx.x * 64;

    for (int i = tid; i < 64 * NC / 4; i += nth)
        ((float4*)Ws)[i] = ((const float4*)W)[i];

    for (int i = tid; i < 64 * 16; i += nth) {
        int r = i & 63, k4 = i >> 6;
        int gr = row0 + r;
        float4 v = make_float4(0.f, 0.f, 0.f, 0.f);
        if (gr < NN) v = ((const float4*)(in + (size_t)gr * 64))[k4];
        XsT[(k4 * 4 + 0) * 68 + r] = v.x;
        XsT[(k4 * 4 + 1) * 68 + r] = v.y;
        XsT[(k4 * 4 + 2) * 68 + r] = v.z;
        XsT[(k4 * 4 + 3) * 68 + r] = v.w;
    }
    __syncthreads();

    int tc = tid % (NC / 4), tr = tid / (NC / 4);
    int c0 = tc * 4, r0 = tr * 4;
    float acc[4][4];
    #pragma unroll
    for (int i = 0; i < 4; i++)
        #pragma unroll
        for (int j = 0; j < 4; j++) acc[i][j] = 0.f;

    #pragma unroll 8
    for (int k = 0; k < 64; k++) {
        float4 b = *(const float4*)&Ws[k * NC + c0];
        float4 a = *(const float4*)&XsT[k * 68 + r0];
        acc[0][0] += a.x * b.x; acc[0][1] += a.x * b.y; acc[0][2] += a.x * b.z; acc[0][3] += a.x * b.w;
        acc[1][0] += a.y * b.x; acc[1][1] += a.y * b.y; acc[1][2] += a.y * b.z; acc[1][3] += a.y * b.w;
        acc[2][0] += a.z * b.x; acc[2][1] += a.z * b.y; acc[2][2] += a.z * b.z; acc[2][3] += a.z * b.w;
        acc[3][0] += a.w * b.x; acc[3][1] += a.w * b.y; acc[3][2] += a.w * b.z; acc[3][3] += a.w * b.w;
    }

    #pragma unroll
    for (int i = 0; i < 4; i++) {
        int gr = row0 + r0 + i;
        if (gr < NN) {
            __half2* o2 = (__half2*)(out + (size_t)gr * OS + c0);
            o2[0] = __floats2half2_rn(acc[i][0], acc[i][1]);
            o2[1] = __floats2half2_rn(acc[i][2], acc[i][3]);
        }
    }
}

// ---------------- aggregation (NC=64): warp per dst node, fp16 gather ----------------
__global__ void k_agg64(const __half2* __restrict__ h, const float* __restrict__ bias,
                        const float* __restrict__ t, float* __restrict__ out) {
    int wid  = (blockIdx.x * blockDim.x + threadIdx.x) >> 5;
    int lane = threadIdx.x & 31;
    if (wid >= NN) return;
    int e = g_start[wid], en = e + g_deg[wid];
    float ax = 0.f, ay = 0.f;
    while (e + 4 <= en) {
        int2 c0 = __ldg(&g_cw[e]);
        int2 c1 = __ldg(&g_cw[e + 1]);
        int2 c2 = __ldg(&g_cw[e + 2]);
        int2 c3 = __ldg(&g_cw[e + 3]);
        __half2 v0 = __ldg(h + (size_t)c0.x * 32 + lane);
        __half2 v1 = __ldg(h + (size_t)c1.x * 32 + lane);
        __half2 v2 = __ldg(h + (size_t)c2.x * 32 + lane);
        __half2 v3 = __ldg(h + (size_t)c3.x * 32 + lane);
        float2 f;
        f = __half22float2(v0); ax += __int_as_float(c0.y) * f.x; ay += __int_as_float(c0.y) * f.y;
        f = __half22float2(v1); ax += __int_as_float(c1.y) * f.x; ay += __int_as_float(c1.y) * f.y;
        f = __half22float2(v2); ax += __int_as_float(c2.y) * f.x; ay += __int_as_float(c2.y) * f.y;
        f = __half22float2(v3); ax += __int_as_float(c3.y) * f.x; ay += __int_as_float(c3.y) * f.y;
        e += 4;
    }
    while (e < en) {
        int2 c = __ldg(&g_cw[e++]);
        float2 f = __half22float2(__ldg(h + (size_t)c.x * 32 + lane));
        float w = __int_as_float(c.y);
        ax += w * f.x; ay += w * f.y;
    }
    float sd = g_s[wid];
    int c = lane * 2;
    ax += bias[c]     + sd * t[c];
    ay += bias[c + 1] + sd * t[c + 1];
    ((float2*)out)[(size_t)wid * 32 + lane] = make_float2(ax, ay);
}

// ---------------- aggregation (NC=40, h stride 64 halves) + fused log_softmax ----------------
__global__ void k_agg40lsm(const __half2* __restrict__ h, const float* __restrict__ bias,
                           const float* __restrict__ t, float* __restrict__ emb,
                           float* __restrict__ out) {
    int wid  = (blockIdx.x * blockDim.x + threadIdx.x) >> 5;
    int lane = threadIdx.x & 31;
    if (wid >= NN) return;
    bool act = lane < 20;
    int e = g_start[wid], en = e + g_deg[wid];
    float ax = 0.f, ay = 0.f;
    while (e + 4 <= en) {
        int2 c0 = __ldg(&g_cw[e]);
        int2 c1 = __ldg(&g_cw[e + 1]);
        int2 c2 = __ldg(&g_cw[e + 2]);
        int2 c3 = __ldg(&g_cw[e + 3]);
        if (act) {
            float2 f;
            f = __half22float2(__ldg(h + (size_t)c0.x * 32 + lane));
            ax += __int_as_float(c0.y) * f.x; ay += __int_as_float(c0.y) * f.y;
            f = __half22float2(__ldg(h + (size_t)c1.x * 32 + lane));
            ax += __int_as_float(c1.y) * f.x; ay += __int_as_float(c1.y) * f.y;
            f = __half22float2(__ldg(h + (size_t)c2.x * 32 + lane));
            ax += __int_as_float(c2.y) * f.x; ay += __int_as_float(c2.y) * f.y;
            f = __half22float2(__ldg(h + (size_t)c3.x * 32 + lane));
            ax += __int_as_float(c3.y) * f.x; ay += __int_as_float(c3.y) * f.y;
        }
        e += 4;
    }
    while (e < en) {
        int2 c = __ldg(&g_cw[e++]);
        if (act) {
            float2 f = __half22float2(__ldg(h + (size_t)c.x * 32 + lane));
            float w = __int_as_float(c.y);
            ax += w * f.x; ay += w * f.y;
        }
    }
    float sd = g_s[wid];
    float v0 = 0.f, v1 = 0.f;
    if (act) {
        int c = lane * 2;
        v0 = ax + bias[c]     + sd * t[c];
        v1 = ay + bias[c + 1] + sd * t[c + 1];
        ((float2*)emb)[(size_t)wid * 20 + lane] = make_float2(v0, v1);
    }
    float m = act ? fmaxf(v0, v1) : -3.4e38f;
    #pragma unroll
    for (int o = 16; o > 0; o >>= 1) m = fmaxf(m, __shfl_xor_sync(0xffffffffu, m, o));
    float s = act ? (__expf(v0 - m) + __expf(v1 - m)) : 0.f;
    #pragma unroll
    for (int o = 16; o > 0; o >>= 1) s += __shfl_xor_sync(0xffffffffu, s, o);
    float lse = m + logf(s);
    if (act)
        ((float2*)out)[(size_t)wid * 20 + lane] = make_float2(v0 - lse, v1 - lse);
}

// ---------------- BN column stats (sum, sumsq) ----------------
__global__ void k_stats(const float* __restrict__ a, float* __restrict__ st) {
    int col = threadIdx.x & 63, sub = threadIdx.x >> 6;
    float s = 0.f, q = 0.f;
    for (int r = blockIdx.x * 4 + sub; r < NN; r += gridDim.x * 4) {
        float v = a[(size_t)r * 64 + col];
        s += v; q += v * v;
    }
    __shared__ float shs[256], shq[256];
    shs[threadIdx.x] = s; shq[threadIdx.x] = q;
    __syncthreads();
    if (sub == 0) {
        s = shs[col] + shs[col + 64] + shs[col + 128] + shs[col + 192];
        q = shq[col] + shq[col + 64] + shq[col + 128] + shq[col + 192];
        atomicAdd(&st[col], s);
        atomicAdd(&st[col + 64], q);
    }
}

// ---------------- fold BN into next layer's weights ----------------
// bn(x)[k] = x*a[k] + c[k];  (bn(h))@W = h@(a (.) W) + c^T W
// t[j] = c^T W passes through propagation scaled by s_d (handled in agg).
template <int NCN>
__global__ void k_fold(const float* __restrict__ W, const float* __restrict__ g,
                       const float* __restrict__ be, const float* __restrict__ st,
                       float* __restrict__ Wf, float* __restrict__ t) {
    __shared__ float a[64], c[64];
    int tid = threadIdx.x;
    if (tid < 64) {
        float mean = st[tid] * (1.f / NN);
        float var  = st[tid + 64] * (1.f / NN) - mean * mean;
        float ai = g[tid] * rsqrtf(var + EPSV);
        a[tid] = ai;
        c[tid] = be[tid] - mean * ai;
    }
    __syncthreads();
    for (int i = tid; i < 64 * NCN; i += 256) Wf[i] = a[i / NCN] * W[i];
    if (tid < NCN) {
        float tv = 0.f;
        #pragma unroll
        for (int k = 0; k < 64; k++) tv += c[k] * W[k * NCN + tid];
        t[tid] = tv;
    }
}

// ---------------- launcher ----------------
extern "C" void kernel_launch(void* const* d_in, const int* in_sizes, int n_in,
                              void* d_out, int out_size) {
    const float* x   = (const float*)d_in[0];
    const void*  ei  = d_in[1];                 // int32 or int64, detected on device
    const float* W1  = (const float*)d_in[2];
    const float* b1  = (const float*)d_in[3];
    const float* W2  = (const float*)d_in[4];
    const float* b2  = (const float*)d_in[5];
    const float* W3  = (const float*)d_in[6];
    const float* b3  = (const float*)d_in[7];
    const float* g1  = (const float*)d_in[8];
    const float* be1 = (const float*)d_in[9];
    const float* g2  = (const float*)d_in[10];
    const float* be2 = (const float*)d_in[11];
    float* out = (float*)d_out;

    __half2* hP; float *aP, *W2fP, *W3fP, *t2P, *t3P, *z64P, *s1P, *s2P;
    cudaGetSymbolAddress((void**)&hP,   g_h);
    cudaGetSymbolAddress((void**)&aP,   g_agg);
    cudaGetSymbolAddress((void**)&W2fP, g_W2f);
    cudaGetSymbolAddress((void**)&W3fP, g_W3f);
    cudaGetSymbolAddress((void**)&t2P,  g_t2);
    cudaGetSymbolAddress((void**)&t3P,  g_t3);
    cudaGetSymbolAddress((void**)&z64P, g_zero64);
    cudaGetSymbolAddress((void**)&s1P,  g_stats1);
    cudaGetSymbolAddress((void**)&s2P,  g_stats2);

    // output layout: (out, emb) concatenated
    float* emb = (out_size >= 2 * NN * 40) ? (out + NN * 40) : aP;

    // graph build
    k_init  <<<(NN + 255) / 256, 256>>>();
    k_detect<<<256, 256>>>((const long long*)ei);
    k_degree<<<(EE + 255) / 256, 256>>>(ei);
    k_dinv  <<<(NN + 255) / 256, 256>>>();
    k_scanA <<<NB, 256>>>();
    k_scanB <<<1, 32>>>();
    k_scanC <<<NB, 256>>>();
    k_fill  <<<(MM + 255) / 256, 256>>>(ei);

    // layer 1
    k_gemm<64, 64><<<(NN + 63) / 64, 256>>>(x, W1, (__half*)hP);
    k_agg64       <<<(NN + 7) / 8, 256>>>(hP, b1, z64P, aP);
    k_stats       <<<256, 256>>>(aP, s1P);
    k_fold<64>    <<<1, 256>>>(W2, g1, be1, s1P, W2fP, t2P);

    // layer 2 (BN1 folded into W2)
    k_gemm<64, 64><<<(NN + 63) / 64, 256>>>(aP, W2fP, (__half*)hP);
    k_agg64       <<<(NN + 7) / 8, 256>>>(hP, b2, t2P, aP);
    k_stats       <<<256, 256>>>(aP, s2P);
    k_fold<40>    <<<1, 256>>>(W3, g2, be2, s2P, W3fP, t3P);

    // layer 3 (BN2 folded into W3, h padded to 64-half rows) -> emb + log_softmax fused
    k_gemm<40, 64><<<(NN + 63) / 64, 160>>>(aP, W3fP, (__half*)hP);
    k_agg40lsm    <<<(NN + 7) / 8, 256>>>(hP, b3, t3P, emb, out);
}

// round 4
// speedup vs baseline: 1.3258x; 1.3258x over previous
#include <cuda_runtime.h>
#include <math.h>

#define NN 100000
#define EE 1600000
#define MM (EE + NN)
#define NB 49            // ceil(NN / 2048)
#define EPSV 1e-5f

// ---------------- scratch (static device allocations; no cudaMalloc) ----------------
__device__ int   g_is64;
__device__ int   g_deg[NN];
__device__ float g_dinv[NN];
__device__ int   g_start[NN];
__device__ int   g_cursor[NN];
__device__ int   g_tilesum[NB];
__device__ int   g_tileoff[NB];
__device__ int2  g_cw[MM];          // (src, norm-bits) per CSR slot
__device__ float g_s[NN];           // row sums of normalized adjacency
__device__ float g_h[NN * 64];      // GEMM output (fp32)
__device__ float g_agg[NN * 64];    // aggregation output (fp32)
__device__ float g_stats1[128];     // [sum(64), sumsq(64)]
__device__ float g_stats2[128];
__device__ float g_W2f[64 * 64];    // BN1-folded W2
__device__ float g_W3f[64 * 40];    // BN2-folded W3
__device__ float g_t2[64];
__device__ float g_t3[64];
__device__ float g_zero64[64];

// ---------------- graph build ----------------
__global__ void k_init() {
    int i = blockIdx.x * blockDim.x + threadIdx.x;
    if (i < NN) { g_deg[i] = 1; g_s[i] = 0.f; }      // self-loop
    if (i < 128) { g_stats1[i] = 0.f; g_stats2[i] = 0.f; }
    if (i < 64) g_zero64[i] = 0.f;
    if (i == 0) g_is64 = 1;
}

// Sampled dtype detect: if buffer is int64, sampled entries are edge_index[0]
// values in [0, NN). If int32, the 64-bit reinterpretation's high word is the
// next int32 index (nonzero w.p. 1-1e-5 per sample) -> out of range -> flag 0.
__global__ void k_detect(const long long* __restrict__ p) {
    int i = blockIdx.x * blockDim.x + threadIdx.x;   // 65536 threads
    long long v = p[(size_t)i * 24];                 // stays < EE int64 slots
    if (v < 0 || v >= NN) g_is64 = 0;                // benign race: all store 0
}

__device__ __forceinline__ long long edge_at(const void* ei, int idx) {
    if (g_is64) return ((const long long*)ei)[idx];
    return (long long)((const int*)ei)[idx];
}

__global__ void k_degree(const void* __restrict__ ei) {
    int i = blockIdx.x * blockDim.x + threadIdx.x;
    if (i >= EE) return;
    long long d = edge_at(ei, EE + i);
    if ((unsigned long long)d < (unsigned long long)NN)
        atomicAdd(&g_deg[(int)d], 1);
}

__global__ void k_dinv() {
    int i = blockIdx.x * blockDim.x + threadIdx.x;
    if (i < NN) g_dinv[i] = rsqrtf((float)g_deg[i]);
}

__global__ void k_scanA() {   // block-tile sums (tile = 2048)
    int base = blockIdx.x * 2048;
    int s = 0;
    for (int i = threadIdx.x; i < 2048; i += 256) {
        int idx = base + i;
        if (idx < NN) s += g_deg[idx];
    }
    __shared__ int sh[256];
    sh[threadIdx.x] = s;
    __syncthreads();
    for (int o = 128; o > 0; o >>= 1) {
        if (threadIdx.x < o) sh[threadIdx.x] += sh[threadIdx.x + o];
        __syncthreads();
    }
    if (threadIdx.x == 0) g_tilesum[blockIdx.x] = sh[0];
}

__global__ void k_scanB() {   // exclusive scan of NB tile sums
    if (threadIdx.x == 0) {
        int a = 0;
        for (int b = 0; b < NB; b++) { g_tileoff[b] = a; a += g_tilesum[b]; }
    }
}

__global__ void k_scanC() {   // intra-tile exclusive scan -> start/cursor
    int tid = threadIdx.x;
    int base = blockIdx.x * 2048 + tid * 8;
    int loc[8];
    int s = 0;
    #pragma unroll
    for (int j = 0; j < 8; j++) {
        int idx = base + j;
        int d = (idx < NN) ? g_deg[idx] : 0;
        loc[j] = s; s += d;
    }
    __shared__ int sh[256];
    sh[tid] = s;
    __syncthreads();
    int run = s;
    for (int o = 1; o < 256; o <<= 1) {
        int v = (tid >= o) ? sh[tid - o] : 0;
        __syncthreads();
        sh[tid] += v;
        __syncthreads();
    }
    int off = g_tileoff[blockIdx.x] + sh[tid] - run;
    #pragma unroll
    for (int j = 0; j < 8; j++) {
        int idx = base + j;
        if (idx < NN) { int p = off + loc[j]; g_start[idx] = p; g_cursor[idx] = p; }
    }
}

// CSR fill + fused row-sum (s_d accumulated via float atomics).
__global__ void k_fill(const void* __restrict__ ei) {
    int i = blockIdx.x * blockDim.x + threadIdx.x;
    if (i >= MM) return;
    int s, d;
    if (i < EE) {
        long long ls = edge_at(ei, i);
        long long ld = edge_at(ei, EE + i);
        if ((unsigned long long)ls >= (unsigned long long)NN) return;
        if ((unsigned long long)ld >= (unsigned long long)NN) return;
        s = (int)ls; d = (int)ld;
    } else {
        s = i - EE; d = s;
    }
    float w = g_dinv[s] * g_dinv[d];
    int pos = atomicAdd(&g_cursor[d], 1);
    g_cw[pos] = make_int2(s, __float_as_int(w));
    atomicAdd(&g_s[d], w);
}

// ---------------- GEMM: out[N x NC] = in[N x 64] @ W[64 x NC] (all fp32) ----------------
// blockDim must be (NC/4)*16; block tile = 64 rows x NC cols.
template <int NC>
__global__ void k_gemm(const float* __restrict__ in, const float* __restrict__ W,
                       float* __restrict__ out) {
    __shared__ float XsT[64 * 68];   // [k][row], padded
    __shared__ float Ws[64 * NC];    // [k][j]
    const int nth = (NC / 4) * 16;
    int tid = threadIdx.x;
    int row0 = blockIdx.x * 64;

    for (int i = tid; i < 64 * NC / 4; i += nth)
        ((float4*)Ws)[i] = ((const float4*)W)[i];

    for (int i = tid; i < 64 * 16; i += nth) {
        int r = i & 63, k4 = i >> 6;
        int gr = row0 + r;
        float4 v = make_float4(0.f, 0.f, 0.f, 0.f);
        if (gr < NN) v = ((const float4*)(in + (size_t)gr * 64))[k4];
        XsT[(k4 * 4 + 0) * 68 + r] = v.x;
        XsT[(k4 * 4 + 1) * 68 + r] = v.y;
        XsT[(k4 * 4 + 2) * 68 + r] = v.z;
        XsT[(k4 * 4 + 3) * 68 + r] = v.w;
    }
    __syncthreads();

    int tc = tid % (NC / 4), tr = tid / (NC / 4);
    int c0 = tc * 4, r0 = tr * 4;
    float acc[4][4];
    #pragma unroll
    for (int i = 0; i < 4; i++)
        #pragma unroll
        for (int j = 0; j < 4; j++) acc[i][j] = 0.f;

    #pragma unroll 8
    for (int k = 0; k < 64; k++) {
        float4 b = *(const float4*)&Ws[k * NC + c0];
        float4 a = *(const float4*)&XsT[k * 68 + r0];
        acc[0][0] += a.x * b.x; acc[0][1] += a.x * b.y; acc[0][2] += a.x * b.z; acc[0][3] += a.x * b.w;
        acc[1][0] += a.y * b.x; acc[1][1] += a.y * b.y; acc[1][2] += a.y * b.z; acc[1][3] += a.y * b.w;
        acc[2][0] += a.z * b.x; acc[2][1] += a.z * b.y; acc[2][2] += a.z * b.z; acc[2][3] += a.z * b.w;
        acc[3][0] += a.w * b.x; acc[3][1] += a.w * b.y; acc[3][2] += a.w * b.z; acc[3][3] += a.w * b.w;
    }

    #pragma unroll
    for (int i = 0; i < 4; i++) {
        int gr = row0 + r0 + i;
        if (gr < NN)
            *(float4*)&out[(size_t)gr * NC + c0] =
                make_float4(acc[i][0], acc[i][1], acc[i][2], acc[i][3]);
    }
}

// ---------------- aggregation (NC=64): warp per dst, float2 lanes, 4x unroll ----------------
__global__ void k_agg64(const float* __restrict__ h, const float* __restrict__ bias,
                        const float* __restrict__ t, float* __restrict__ out) {
    int wid  = (blockIdx.x * blockDim.x + threadIdx.x) >> 5;
    int lane = threadIdx.x & 31;
    if (wid >= NN) return;
    const float2* h2 = (const float2*)h;
    int e = g_start[wid], en = e + g_deg[wid];
    float ax = 0.f, ay = 0.f;
    while (e + 4 <= en) {
        int2 c0 = __ldg(&g_cw[e]);
        int2 c1 = __ldg(&g_cw[e + 1]);
        int2 c2 = __ldg(&g_cw[e + 2]);
        int2 c3 = __ldg(&g_cw[e + 3]);
        float2 v0 = __ldg(h2 + (size_t)c0.x * 32 + lane);
        float2 v1 = __ldg(h2 + (size_t)c1.x * 32 + lane);
        float2 v2 = __ldg(h2 + (size_t)c2.x * 32 + lane);
        float2 v3 = __ldg(h2 + (size_t)c3.x * 32 + lane);
        float w0 = __int_as_float(c0.y), w1 = __int_as_float(c1.y);
        float w2 = __int_as_float(c2.y), w3 = __int_as_float(c3.y);
        ax += w0 * v0.x; ay += w0 * v0.y;
        ax += w1 * v1.x; ay += w1 * v1.y;
        ax += w2 * v2.x; ay += w2 * v2.y;
        ax += w3 * v3.x; ay += w3 * v3.y;
        e += 4;
    }
    while (e < en) {
        int2 c = __ldg(&g_cw[e++]);
        float2 v = __ldg(h2 + (size_t)c.x * 32 + lane);
        float w = __int_as_float(c.y);
        ax += w * v.x; ay += w * v.y;
    }
    float sd = g_s[wid];
    int c = lane * 2;
    ax += bias[c]     + sd * t[c];
    ay += bias[c + 1] + sd * t[c + 1];
    ((float2*)out)[(size_t)wid * 32 + lane] = make_float2(ax, ay);
}

// ---------------- aggregation (NC=40) + fused log_softmax ----------------
__global__ void k_agg40lsm(const float* __restrict__ h, const float* __restrict__ bias,
                           const float* __restrict__ t, float* __restrict__ emb,
                           float* __restrict__ out) {
    int wid  = (blockIdx.x * blockDim.x + threadIdx.x) >> 5;
    int lane = threadIdx.x & 31;
    if (wid >= NN) return;
    bool act = lane < 20;
    int ln = act ? lane : 0;                 // keep loads in-bounds for idle lanes
    const float2* h2 = (const float2*)h;     // row stride = 20 float2
    int e = g_start[wid], en = e + g_deg[wid];
    float ax = 0.f, ay = 0.f;
    while (e + 4 <= en) {
        int2 c0 = __ldg(&g_cw[e]);
        int2 c1 = __ldg(&g_cw[e + 1]);
        int2 c2 = __ldg(&g_cw[e + 2]);
        int2 c3 = __ldg(&g_cw[e + 3]);
        float2 v0 = __ldg(h2 + (size_t)c0.x * 20 + ln);
        float2 v1 = __ldg(h2 + (size_t)c1.x * 20 + ln);
        float2 v2 = __ldg(h2 + (size_t)c2.x * 20 + ln);
        float2 v3 = __ldg(h2 + (size_t)c3.x * 20 + ln);
        float w0 = __int_as_float(c0.y), w1 = __int_as_float(c1.y);
        float w2 = __int_as_float(c2.y), w3 = __int_as_float(c3.y);
        ax += w0 * v0.x; ay += w0 * v0.y;
        ax += w1 * v1.x; ay += w1 * v1.y;
        ax += w2 * v2.x; ay += w2 * v2.y;
        ax += w3 * v3.x; ay += w3 * v3.y;
        e += 4;
    }
    while (e < en) {
        int2 c = __ldg(&g_cw[e++]);
        float2 v = __ldg(h2 + (size_t)c.x * 20 + ln);
        float w = __int_as_float(c.y);
        ax += w * v.x; ay += w * v.y;
    }
    float sd = g_s[wid];
    float v0 = 0.f, v1 = 0.f;
    if (act) {
        int c = lane * 2;
        v0 = ax + bias[c]     + sd * t[c];
        v1 = ay + bias[c + 1] + sd * t[c + 1];
        ((float2*)emb)[(size_t)wid * 20 + lane] = make_float2(v0, v1);
    }
    float m = act ? fmaxf(v0, v1) : -3.4e38f;
    #pragma unroll
    for (int o = 16; o > 0; o >>= 1) m = fmaxf(m, __shfl_xor_sync(0xffffffffu, m, o));
    float s = act ? (__expf(v0 - m) + __expf(v1 - m)) : 0.f;
    #pragma unroll
    for (int o = 16; o > 0; o >>= 1) s += __shfl_xor_sync(0xffffffffu, s, o);
    float lse = m + logf(s);
    if (act)
        ((float2*)out)[(size_t)wid * 20 + lane] = make_float2(v0 - lse, v1 - lse);
}

// ---------------- BN column stats (sum, sumsq) ----------------
__global__ void k_stats(const float* __restrict__ a, float* __restrict__ st) {
    int col = threadIdx.x & 63, sub = threadIdx.x >> 6;
    float s = 0.f, q = 0.f;
    for (int r = blockIdx.x * 4 + sub; r < NN; r += gridDim.x * 4) {
        float v = a[(size_t)r * 64 + col];
        s += v; q += v * v;
    }
    __shared__ float shs[256], shq[256];
    shs[threadIdx.x] = s; shq[threadIdx.x] = q;
    __syncthreads();
    if (sub == 0) {
        s = shs[col] + shs[col + 64] + shs[col + 128] + shs[col + 192];
        q = shq[col] + shq[col + 64] + shq[col + 128] + shq[col + 192];
        atomicAdd(&st[col], s);
        atomicAdd(&st[col + 64], q);
    }
}

// ---------------- fold BN into next layer's weights ----------------
// bn(x)[k] = x*a[k] + c[k];  (bn(h))@W = h@(a (.) W) + c^T W
// t[j] = c^T W passes through propagation scaled by s_d (handled in agg).
template <int NCN>
__global__ void k_fold(const float* __restrict__ W, const float* __restrict__ g,
                       const float* __restrict__ be, const float* __restrict__ st,
                       float* __restrict__ Wf, float* __restrict__ t) {
    __shared__ float a[64], c[64];
    int tid = threadIdx.x;
    if (tid < 64) {
        float mean = st[tid] * (1.f / NN);
        float var  = st[tid + 64] * (1.f / NN) - mean * mean;
        float ai = g[tid] * rsqrtf(var + EPSV);
        a[tid] = ai;
        c[tid] = be[tid] - mean * ai;
    }
    __syncthreads();
    for (int i = tid; i < 64 * NCN; i += 256) Wf[i] = a[i / NCN] * W[i];
    if (tid < NCN) {
        float tv = 0.f;
        #pragma unroll
        for (int k = 0; k < 64; k++) tv += c[k] * W[k * NCN + tid];
        t[tid] = tv;
    }
}

// ---------------- launcher ----------------
extern "C" void kernel_launch(void* const* d_in, const int* in_sizes, int n_in,
                              void* d_out, int out_size) {
    const float* x   = (const float*)d_in[0];
    const void*  ei  = d_in[1];                 // int32 or int64, detected on device
    const float* W1  = (const float*)d_in[2];
    const float* b1  = (const float*)d_in[3];
    const float* W2  = (const float*)d_in[4];
    const float* b2  = (const float*)d_in[5];
    const float* W3  = (const float*)d_in[6];
    const float* b3  = (const float*)d_in[7];
    const float* g1  = (const float*)d_in[8];
    const float* be1 = (const float*)d_in[9];
    const float* g2  = (const float*)d_in[10];
    const float* be2 = (const float*)d_in[11];
    float* out = (float*)d_out;

    float *hP, *aP, *W2fP, *W3fP, *t2P, *t3P, *z64P, *s1P, *s2P;
    cudaGetSymbolAddress((void**)&hP,   g_h);
    cudaGetSymbolAddress((void**)&aP,   g_agg);
    cudaGetSymbolAddress((void**)&W2fP, g_W2f);
    cudaGetSymbolAddress((void**)&W3fP, g_W3f);
    cudaGetSymbolAddress((void**)&t2P,  g_t2);
    cudaGetSymbolAddress((void**)&t3P,  g_t3);
    cudaGetSymbolAddress((void**)&z64P, g_zero64);
    cudaGetSymbolAddress((void**)&s1P,  g_stats1);
    cudaGetSymbolAddress((void**)&s2P,  g_stats2);

    // output layout: (out, emb) concatenated
    float* emb = (out_size >= 2 * NN * 40) ? (out + NN * 40) : aP;

    // graph build
    k_init  <<<(NN + 255) / 256, 256>>>();
    k_detect<<<256, 256>>>((const long long*)ei);
    k_degree<<<(EE + 255) / 256, 256>>>(ei);
    k_dinv  <<<(NN + 255) / 256, 256>>>();
    k_scanA <<<NB, 256>>>();
    k_scanB <<<1, 32>>>();
    k_scanC <<<NB, 256>>>();
    k_fill  <<<(MM + 255) / 256, 256>>>(ei);

    // layer 1
    k_gemm<64><<<(NN + 63) / 64, 256>>>(x, W1, hP);
    k_agg64   <<<(NN + 7) / 8, 256>>>(hP, b1, z64P, aP);
    k_stats   <<<256, 256>>>(aP, s1P);
    k_fold<64><<<1, 256>>>(W2, g1, be1, s1P, W2fP, t2P);

    // layer 2 (BN1 folded into W2)
    k_gemm<64><<<(NN + 63) / 64, 256>>>(aP, W2fP, hP);
    k_agg64   <<<(NN + 7) / 8, 256>>>(hP, b2, t2P, aP);
    k_stats   <<<256, 256>>>(aP, s2P);
    k_fold<40><<<1, 256>>>(W3, g2, be2, s2P, W3fP, t3P);

    // layer 3 (BN2 folded into W3) -> emb + fused log_softmax -> out
    k_gemm<40><<<(NN + 63) / 64, 160>>>(aP, W3fP, hP);
    k_agg40lsm<<<(NN + 7) / 8, 256>>>(hP, b3, t3P, emb, out);
}

// round 5
// speedup vs baseline: 1.4104x; 1.0638x over previous
#include <cuda_runtime.h>
#include <math.h>

#define NN 100000
#define EE 1600000
#define MM (EE + NN)
#define NB 49            // ceil(NN / 2048)
#define EPSV 1e-5f

// ---------------- scratch (static device allocations; no cudaMalloc) ----------------
__device__ int   g_is64 = 1;        // detection only ever clears -> stable across replays
__device__ int   g_deg[NN];
__device__ float g_dinv[NN];
__device__ int   g_start[NN];
__device__ int   g_cursor[NN];
__device__ int   g_tilesum[NB];
__device__ int   g_tileoff[NB];
__device__ int2  g_cw[MM];          // (src, norm-bits) per CSR slot
__device__ float g_s[NN];           // row sums of normalized adjacency
__device__ __align__(16) float g_h[NN * 64];      // GEMM output (fp32)
__device__ __align__(16) float g_agg[NN * 64];    // aggregation output (fp32)
__device__ float g_stats1[128];     // [sum(64), sumsq(64)]
__device__ float g_stats2[128];
__device__ float g_W2f[64 * 64];    // BN1-folded W2
__device__ float g_W3f[64 * 40];    // BN2-folded W3
__device__ float g_t2[64];
__device__ float g_t3[64];
__device__ __align__(16) float g_zero64[64];

// ---------------- graph init + sampled dtype detect ----------------
// If the edge buffer is int64, sampled 64-bit entries are edge_index[0] values
// in [0, NN). If it's int32, each 64-bit reinterpretation's high word is the
// next int32 index (nonzero w.p. 1-1e-5 per sample) -> out of range -> clear flag.
__global__ void k_init(const long long* __restrict__ p) {
    int i = blockIdx.x * blockDim.x + threadIdx.x;
    if (i < NN) { g_deg[i] = 1; g_s[i] = 0.f; }      // self-loop
    if (i < 128) { g_stats1[i] = 0.f; g_stats2[i] = 0.f; }
    if (i < 64) g_zero64[i] = 0.f;
    if (i < 65536) {
        long long v = p[(size_t)i * 24];             // max idx < EE int64 slots
        if (v < 0 || v >= NN) g_is64 = 0;            // only writes 0: race-free
    }
}

__device__ __forceinline__ long long edge_at(const void* ei, int idx) {
    if (g_is64) return ((const long long*)ei)[idx];
    return (long long)((const int*)ei)[idx];
}

__global__ void k_degree(const void* __restrict__ ei) {
    int i = blockIdx.x * blockDim.x + threadIdx.x;
    if (i >= EE) return;
    long long d = edge_at(ei, EE + i);
    if ((unsigned long long)d < (unsigned long long)NN)
        atomicAdd(&g_deg[(int)d], 1);
}

__global__ void k_scanA() {   // block-tile sums (tile = 2048) + fused dinv
    int base = blockIdx.x * 2048;
    int s = 0;
    for (int i = threadIdx.x; i < 2048; i += 256) {
        int idx = base + i;
        if (idx < NN) {
            int d = g_deg[idx];
            s += d;
            g_dinv[idx] = rsqrtf((float)d);
        }
    }
    __shared__ int sh[256];
    sh[threadIdx.x] = s;
    __syncthreads();
    for (int o = 128; o > 0; o >>= 1) {
        if (threadIdx.x < o) sh[threadIdx.x] += sh[threadIdx.x + o];
        __syncthreads();
    }
    if (threadIdx.x == 0) g_tilesum[blockIdx.x] = sh[0];
}

__global__ void k_scanB() {   // exclusive scan of NB tile sums
    if (threadIdx.x == 0) {
        int a = 0;
        for (int b = 0; b < NB; b++) { g_tileoff[b] = a; a += g_tilesum[b]; }
    }
}

__global__ void k_scanC() {   // intra-tile exclusive scan -> start/cursor
    int tid = threadIdx.x;
    int base = blockIdx.x * 2048 + tid * 8;
    int loc[8];
    int s = 0;
    #pragma unroll
    for (int j = 0; j < 8; j++) {
        int idx = base + j;
        int d = (idx < NN) ? g_deg[idx] : 0;
        loc[j] = s; s += d;
    }
    __shared__ int sh[256];
    sh[tid] = s;
    __syncthreads();
    int run = s;
    for (int o = 1; o < 256; o <<= 1) {
        int v = (tid >= o) ? sh[tid - o] : 0;
        __syncthreads();
        sh[tid] += v;
        __syncthreads();
    }
    int off = g_tileoff[blockIdx.x] + sh[tid] - run;
    #pragma unroll
    for (int j = 0; j < 8; j++) {
        int idx = base + j;
        if (idx < NN) { int p = off + loc[j]; g_start[idx] = p; g_cursor[idx] = p; }
    }
}

// CSR fill + fused row-sum (s_d accumulated via float atomics).
__global__ void k_fill(const void* __restrict__ ei) {
    int i = blockIdx.x * blockDim.x + threadIdx.x;
    if (i >= MM) return;
    int s, d;
    if (i < EE) {
        long long ls = edge_at(ei, i);
        long long ld = edge_at(ei, EE + i);
        if ((unsigned long long)ls >= (unsigned long long)NN) return;
        if ((unsigned long long)ld >= (unsigned long long)NN) return;
        s = (int)ls; d = (int)ld;
    } else {
        s = i - EE; d = s;
    }
    float w = g_dinv[s] * g_dinv[d];
    int pos = atomicAdd(&g_cursor[d], 1);
    g_cw[pos] = make_int2(s, __float_as_int(w));
    atomicAdd(&g_s[d], w);
}

// ---------------- GEMM: out[N x NC] = in[N x 64] @ W[64 x NC] (all fp32) ----------------
// blockDim must be (NC/4)*16; block tile = 64 rows x NC cols.
template <int NC>
__global__ void k_gemm(const float* __restrict__ in, const float* __restrict__ W,
                       float* __restrict__ out) {
    __shared__ float XsT[64 * 68];   // [k][row], padded
    __shared__ float Ws[64 * NC];    // [k][j]
    const int nth = (NC / 4) * 16;
    int tid = threadIdx.x;
    int row0 = blockIdx.x * 64;

    for (int i = tid; i < 64 * NC / 4; i += nth)
        ((float4*)Ws)[i] = ((const float4*)W)[i];

    for (int i = tid; i < 64 * 16; i += nth) {
        int r = i & 63, k4 = i >> 6;
        int gr = row0 + r;
        float4 v = make_float4(0.f, 0.f, 0.f, 0.f);
        if (gr < NN) v = ((const float4*)(in + (size_t)gr * 64))[k4];
        XsT[(k4 * 4 + 0) * 68 + r] = v.x;
        XsT[(k4 * 4 + 1) * 68 + r] = v.y;
        XsT[(k4 * 4 + 2) * 68 + r] = v.z;
        XsT[(k4 * 4 + 3) * 68 + r] = v.w;
    }
    __syncthreads();

    int tc = tid % (NC / 4), tr = tid / (NC / 4);
    int c0 = tc * 4, r0 = tr * 4;
    float acc[4][4];
    #pragma unroll
    for (int i = 0; i < 4; i++)
        #pragma unroll
        for (int j = 0; j < 4; j++) acc[i][j] = 0.f;

    #pragma unroll 8
    for (int k = 0; k < 64; k++) {
        float4 b = *(const float4*)&Ws[k * NC + c0];
        float4 a = *(const float4*)&XsT[k * 68 + r0];
        acc[0][0] += a.x * b.x; acc[0][1] += a.x * b.y; acc[0][2] += a.x * b.z; acc[0][3] += a.x * b.w;
        acc[1][0] += a.y * b.x; acc[1][1] += a.y * b.y; acc[1][2] += a.y * b.z; acc[1][3] += a.y * b.w;
        acc[2][0] += a.z * b.x; acc[2][1] += a.z * b.y; acc[2][2] += a.z * b.z; acc[2][3] += a.z * b.w;
        acc[3][0] += a.w * b.x; acc[3][1] += a.w * b.y; acc[3][2] += a.w * b.z; acc[3][3] += a.w * b.w;
    }

    #pragma unroll
    for (int i = 0; i < 4; i++) {
        int gr = row0 + r0 + i;
        if (gr < NN)
            *(float4*)&out[(size_t)gr * NC + c0] =
                make_float4(acc[i][0], acc[i][1], acc[i][2], acc[i][3]);
    }
}

// ---------------- aggregation (NC=64): half-warp float4, 2 edges/iter, x2 unroll ----------
// Each 16-lane half covers one full 64-float row (float4/lane). Half 0 takes
// even CSR slots, half 1 odd; partial sums combined by shuffle at the end.
__global__ void k_agg64(const float4* __restrict__ h4, const float* __restrict__ bias,
                        const float* __restrict__ t, float* __restrict__ out) {
    int wid  = (blockIdx.x * blockDim.x + threadIdx.x) >> 5;
    int lane = threadIdx.x & 31;
    if (wid >= NN) return;
    int half = lane >> 4, hl = lane & 15;
    int st = g_start[wid], deg = g_deg[wid];
    int pairs = deg >> 1;
    int base = st + half;
    float ax = 0.f, ay = 0.f, az = 0.f, aw = 0.f;
    int i = 0;
    while (i + 2 <= pairs) {
        int2 ca = __ldg(&g_cw[base + 2 * i]);
        int2 cb = __ldg(&g_cw[base + 2 * i + 2]);
        float4 va = __ldg(h4 + (size_t)ca.x * 16 + hl);
        float4 vb = __ldg(h4 + (size_t)cb.x * 16 + hl);
        float wa = __int_as_float(ca.y), wb = __int_as_float(cb.y);
        ax += wa * va.x; ay += wa * va.y; az += wa * va.z; aw += wa * va.w;
        ax += wb * vb.x; ay += wb * vb.y; az += wb * vb.z; aw += wb * vb.w;
        i += 2;
    }
    if (i < pairs) {
        int2 c = __ldg(&g_cw[base + 2 * i]);
        float4 v = __ldg(h4 + (size_t)c.x * 16 + hl);
        float w = __int_as_float(c.y);
        ax += w * v.x; ay += w * v.y; az += w * v.z; aw += w * v.w;
    }
    if ((deg & 1) && half == 0) {          // odd tail edge handled by half 0
        int2 c = __ldg(&g_cw[st + deg - 1]);
        float4 v = __ldg(h4 + (size_t)c.x * 16 + hl);
        float w = __int_as_float(c.y);
        ax += w * v.x; ay += w * v.y; az += w * v.z; aw += w * v.w;
    }
    // combine half-warps (all 32 lanes execute the shuffles)
    ax += __shfl_down_sync(0xffffffffu, ax, 16);
    ay += __shfl_down_sync(0xffffffffu, ay, 16);
    az += __shfl_down_sync(0xffffffffu, az, 16);
    aw += __shfl_down_sync(0xffffffffu, aw, 16);
    if (half == 0) {
        float4 b4 = __ldg((const float4*)bias + hl);
        float4 t4 = __ldg((const float4*)t + hl);
        float sd = g_s[wid];
        float4 o;
        o.x = ax + b4.x + sd * t4.x;
        o.y = ay + b4.y + sd * t4.y;
        o.z = az + b4.z + sd * t4.z;
        o.w = aw + b4.w + sd * t4.w;
        ((float4*)out)[(size_t)wid * 16 + hl] = o;
    }
}

// ---------------- aggregation (NC=40) + fused log_softmax ----------------
__global__ void k_agg40lsm(const float* __restrict__ h, const float* __restrict__ bias,
                           const float* __restrict__ t, float* __restrict__ emb,
                           float* __restrict__ out) {
    int wid  = (blockIdx.x * blockDim.x + threadIdx.x) >> 5;
    int lane = threadIdx.x & 31;
    if (wid >= NN) return;
    bool act = lane < 20;
    int ln = act ? lane : 0;                 // keep loads in-bounds for idle lanes
    const float2* h2 = (const float2*)h;     // row stride = 20 float2
    int e = g_start[wid], en = e + g_deg[wid];
    float ax = 0.f, ay = 0.f;
    while (e + 4 <= en) {
        int2 c0 = __ldg(&g_cw[e]);
        int2 c1 = __ldg(&g_cw[e + 1]);
        int2 c2 = __ldg(&g_cw[e + 2]);
        int2 c3 = __ldg(&g_cw[e + 3]);
        float2 v0 = __ldg(h2 + (size_t)c0.x * 20 + ln);
        float2 v1 = __ldg(h2 + (size_t)c1.x * 20 + ln);
        float2 v2 = __ldg(h2 + (size_t)c2.x * 20 + ln);
        float2 v3 = __ldg(h2 + (size_t)c3.x * 20 + ln);
        float w0 = __int_as_float(c0.y), w1 = __int_as_float(c1.y);
        float w2 = __int_as_float(c2.y), w3 = __int_as_float(c3.y);
        ax += w0 * v0.x; ay += w0 * v0.y;
        ax += w1 * v1.x; ay += w1 * v1.y;
        ax += w2 * v2.x; ay += w2 * v2.y;
        ax += w3 * v3.x; ay += w3 * v3.y;
        e += 4;
    }
    while (e < en) {
        int2 c = __ldg(&g_cw[e++]);
        float2 v = __ldg(h2 + (size_t)c.x * 20 + ln);
        float w = __int_as_float(c.y);
        ax += w * v.x; ay += w * v.y;
    }
    float sd = g_s[wid];
    float v0 = 0.f, v1 = 0.f;
    if (act) {
        int c = lane * 2;
        v0 = ax + bias[c]     + sd * t[c];
        v1 = ay + bias[c + 1] + sd * t[c + 1];
        ((float2*)emb)[(size_t)wid * 20 + lane] = make_float2(v0, v1);
    }
    float m = act ? fmaxf(v0, v1) : -3.4e38f;
    #pragma unroll
    for (int o = 16; o > 0; o >>= 1) m = fmaxf(m, __shfl_xor_sync(0xffffffffu, m, o));
    float s = act ? (__expf(v0 - m) + __expf(v1 - m)) : 0.f;
    #pragma unroll
    for (int o = 16; o > 0; o >>= 1) s += __shfl_xor_sync(0xffffffffu, s, o);
    float lse = m + logf(s);
    if (act)
        ((float2*)out)[(size_t)wid * 20 + lane] = make_float2(v0 - lse, v1 - lse);
}

// ---------------- BN column stats (sum, sumsq) ----------------
__global__ void k_stats(const float* __restrict__ a, float* __restrict__ st) {
    int col = threadIdx.x & 63, sub = threadIdx.x >> 6;
    float s = 0.f, q = 0.f;
    for (int r = blockIdx.x * 4 + sub; r < NN; r += gridDim.x * 4) {
        float v = a[(size_t)r * 64 + col];
        s += v; q += v * v;
    }
    __shared__ float shs[256], shq[256];
    shs[threadIdx.x] = s; shq[threadIdx.x] = q;
    __syncthreads();
    if (sub == 0) {
        s = shs[col] + shs[col + 64] + shs[col + 128] + shs[col + 192];
        q = shq[col] + shq[col + 64] + shq[col + 128] + shq[col + 192];
        atomicAdd(&st[col], s);
        atomicAdd(&st[col + 64], q);
    }
}

// ---------------- fold BN into next layer's weights ----------------
// bn(x)[k] = x*a[k] + c[k];  (bn(h))@W = h@(a (.) W) + c^T W
// t[j] = c^T W passes through propagation scaled by s_d (handled in agg).
template <int NCN>
__global__ void k_fold(const float* __restrict__ W, const float* __restrict__ g,
                       const float* __restrict__ be, const float* __restrict__ st,
                       float* __restrict__ Wf, float* __restrict__ t) {
    __shared__ float a[64], c[64];
    int tid = threadIdx.x;
    if (tid < 64) {
        float mean = st[tid] * (1.f / NN);
        float var  = st[tid + 64] * (1.f / NN) - mean * mean;
        float ai = g[tid] * rsqrtf(var + EPSV);
        a[tid] = ai;
        c[tid] = be[tid] - mean * ai;
    }
    __syncthreads();
    for (int i = tid; i < 64 * NCN; i += 256) Wf[i] = a[i / NCN] * W[i];
    if (tid < NCN) {
        float tv = 0.f;
        #pragma unroll
        for (int k = 0; k < 64; k++) tv += c[k] * W[k * NCN + tid];
        t[tid] = tv;
    }
}

// ---------------- launcher ----------------
extern "C" void kernel_launch(void* const* d_in, const int* in_sizes, int n_in,
                              void* d_out, int out_size) {
    const float* x   = (const float*)d_in[0];
    const void*  ei  = d_in[1];                 // int32 or int64, detected on device
    const float* W1  = (const float*)d_in[2];
    const float* b1  = (const float*)d_in[3];
    const float* W2  = (const float*)d_in[4];
    const float* b2  = (const float*)d_in[5];
    const float* W3  = (const float*)d_in[6];
    const float* b3  = (const float*)d_in[7];
    const float* g1  = (const float*)d_in[8];
    const float* be1 = (const float*)d_in[9];
    const float* g2  = (const float*)d_in[10];
    const float* be2 = (const float*)d_in[11];
    float* out = (float*)d_out;

    float *hP, *aP, *W2fP, *W3fP, *t2P, *t3P, *z64P, *s1P, *s2P;
    cudaGetSymbolAddress((void**)&hP,   g_h);
    cudaGetSymbolAddress((void**)&aP,   g_agg);
    cudaGetSymbolAddress((void**)&W2fP, g_W2f);
    cudaGetSymbolAddress((void**)&W3fP, g_W3f);
    cudaGetSymbolAddress((void**)&t2P,  g_t2);
    cudaGetSymbolAddress((void**)&t3P,  g_t3);
    cudaGetSymbolAddress((void**)&z64P, g_zero64);
    cudaGetSymbolAddress((void**)&s1P,  g_stats1);
    cudaGetSymbolAddress((void**)&s2P,  g_stats2);

    // output layout: (out, emb) concatenated
    float* emb = (out_size >= 2 * NN * 40) ? (out + NN * 40) : aP;

    // graph build
    k_init  <<<(NN + 255) / 256, 256>>>((const long long*)ei);
    k_degree<<<(EE + 255) / 256, 256>>>(ei);
    k_scanA <<<NB, 256>>>();
    k_scanB <<<1, 32>>>();
    k_scanC <<<NB, 256>>>();
    k_fill  <<<(MM + 255) / 256, 256>>>(ei);

    // layer 1
    k_gemm<64><<<(NN + 63) / 64, 256>>>(x, W1, hP);
    k_agg64   <<<(NN + 7) / 8, 256>>>((const float4*)hP, b1, z64P, aP);
    k_stats   <<<256, 256>>>(aP, s1P);
    k_fold<64><<<1, 256>>>(W2, g1, be1, s1P, W2fP, t2P);

    // layer 2 (BN1 folded into W2)
    k_gemm<64><<<(NN + 63) / 64, 256>>>(aP, W2fP, hP);
    k_agg64   <<<(NN + 7) / 8, 256>>>((const float4*)hP, b2, t2P, aP);
    k_stats   <<<256, 256>>>(aP, s2P);
    k_fold<40><<<1, 256>>>(W3, g2, be2, s2P, W3fP, t3P);

    // layer 3 (BN2 folded into W3) -> emb + fused log_softmax -> out
    k_gemm<40><<<(NN + 63) / 64, 160>>>(aP, W3fP, hP);
    k_agg40lsm<<<(NN + 7) / 8, 256>>>(hP, b3, t3P, emb, out);
}

// round 6
// speedup vs baseline: 1.4358x; 1.0181x over previous
#include <cuda_runtime.h>
#include <cuda_fp16.h>
#include <math.h>

#define NN 100000
#define EE 1600000
#define MM (EE + NN)
#define NB 49            // ceil(NN / 2048)
#define EPSV 1e-5f

// ---------------- scratch (static device allocations; no cudaMalloc) ----------------
__device__ int   g_is64 = 1;        // detection only ever clears -> stable across replays
__device__ int   g_deg[NN];
__device__ float g_dinv[NN];
__device__ int   g_start[NN];
__device__ int   g_cursor[NN];
__device__ int   g_tilesum[NB];
__device__ int   g_tileoff[NB];
__device__ int2  g_cw[MM];          // (src, norm-bits) per CSR slot
__device__ float g_s[NN];           // row sums of normalized adjacency
__device__ __align__(16) float g_h[NN * 64];      // GEMM out: fp16 (L1/2) or fp32 (L3)
__device__ __align__(16) float g_agg[NN * 64];    // aggregation output (fp32)
__device__ float g_stats1[128];     // [sum(64), sumsq(64)]
__device__ float g_stats2[128];
__device__ float g_W2f[64 * 64];    // BN1-folded W2
__device__ float g_W3f[64 * 40];    // BN2-folded W3
__device__ float g_t2[64];
__device__ float g_t3[64];
__device__ __align__(16) float g_zero64[64];

// ---------------- graph init + sampled dtype detect ----------------
__global__ void k_init(const long long* __restrict__ p) {
    int i = blockIdx.x * blockDim.x + threadIdx.x;
    if (i < NN) { g_deg[i] = 1; g_s[i] = 0.f; }      // self-loop
    if (i < 128) { g_stats1[i] = 0.f; g_stats2[i] = 0.f; }
    if (i < 64) g_zero64[i] = 0.f;
    if (i < 65536) {
        long long v = p[(size_t)i * 24];             // max idx < EE int64 slots
        if (v < 0 || v >= NN) g_is64 = 0;            // only writes 0: race-free
    }
}

__device__ __forceinline__ long long edge_at(const void* ei, int idx) {
    if (g_is64) return ((const long long*)ei)[idx];
    return (long long)((const int*)ei)[idx];
}

__global__ void k_degree(const void* __restrict__ ei) {
    int i = blockIdx.x * blockDim.x + threadIdx.x;
    if (i >= EE) return;
    long long d = edge_at(ei, EE + i);
    if ((unsigned long long)d < (unsigned long long)NN)
        atomicAdd(&g_deg[(int)d], 1);
}

__global__ void k_scanA() {   // block-tile sums (tile = 2048) + fused dinv
    int base = blockIdx.x * 2048;
    int s = 0;
    for (int i = threadIdx.x; i < 2048; i += 256) {
        int idx = base + i;
        if (idx < NN) {
            int d = g_deg[idx];
            s += d;
            g_dinv[idx] = rsqrtf((float)d);
        }
    }
    __shared__ int sh[256];
    sh[threadIdx.x] = s;
    __syncthreads();
    for (int o = 128; o > 0; o >>= 1) {
        if (threadIdx.x < o) sh[threadIdx.x] += sh[threadIdx.x + o];
        __syncthreads();
    }
    if (threadIdx.x == 0) g_tilesum[blockIdx.x] = sh[0];
}

__global__ void k_scanB() {   // exclusive scan of NB tile sums
    if (threadIdx.x == 0) {
        int a = 0;
        for (int b = 0; b < NB; b++) { g_tileoff[b] = a; a += g_tilesum[b]; }
    }
}

__global__ void k_scanC() {   // intra-tile exclusive scan -> start/cursor
    int tid = threadIdx.x;
    int base = blockIdx.x * 2048 + tid * 8;
    int loc[8];
    int s = 0;
    #pragma unroll
    for (int j = 0; j < 8; j++) {
        int idx = base + j;
        int d = (idx < NN) ? g_deg[idx] : 0;
        loc[j] = s; s += d;
    }
    __shared__ int sh[256];
    sh[tid] = s;
    __syncthreads();
    int run = s;
    for (int o = 1; o < 256; o <<= 1) {
        int v = (tid >= o) ? sh[tid - o] : 0;
        __syncthreads();
        sh[tid] += v;
        __syncthreads();
    }
    int off = g_tileoff[blockIdx.x] + sh[tid] - run;
    #pragma unroll
    for (int j = 0; j < 8; j++) {
        int idx = base + j;
        if (idx < NN) { int p = off + loc[j]; g_start[idx] = p; g_cursor[idx] = p; }
    }
}

// CSR fill + fused row-sum (s_d accumulated via float atomics).
__global__ void k_fill(const void* __restrict__ ei) {
    int i = blockIdx.x * blockDim.x + threadIdx.x;
    if (i >= MM) return;
    int s, d;
    if (i < EE) {
        long long ls = edge_at(ei, i);
        long long ld = edge_at(ei, EE + i);
        if ((unsigned long long)ls >= (unsigned long long)NN) return;
        if ((unsigned long long)ld >= (unsigned long long)NN) return;
        s = (int)ls; d = (int)ld;
    } else {
        s = i - EE; d = s;
    }
    float w = g_dinv[s] * g_dinv[d];
    int pos = atomicAdd(&g_cursor[d], 1);
    g_cw[pos] = make_int2(s, __float_as_int(w));
    atomicAdd(&g_s[d], w);
}

// ---------------- GEMM: out[N x NC] = in[N x 64] @ W[64 x NC] ----------------
// fp32 compute; output fp16 (HOUT, row stride 64 halves) or fp32.
// blockDim must be (NC/4)*16; block tile = 64 rows x NC cols.
template <int NC, bool HOUT>
__global__ void k_gemm(const float* __restrict__ in, const float* __restrict__ W,
                       void* __restrict__ out) {
    __shared__ float XsT[64 * 68];   // [k][row], padded
    __shared__ float Ws[64 * NC];    // [k][j]
    const int nth = (NC / 4) * 16;
    int tid = threadIdx.x;
    int row0 = blockIdx.x * 64;

    for (int i = tid; i < 64 * NC / 4; i += nth)
        ((float4*)Ws)[i] = ((const float4*)W)[i];

    for (int i = tid; i < 64 * 16; i += nth) {
        int r = i & 63, k4 = i >> 6;
        int gr = row0 + r;
        float4 v = make_float4(0.f, 0.f, 0.f, 0.f);
        if (gr < NN) v = ((const float4*)(in + (size_t)gr * 64))[k4];
        XsT[(k4 * 4 + 0) * 68 + r] = v.x;
        XsT[(k4 * 4 + 1) * 68 + r] = v.y;
        XsT[(k4 * 4 + 2) * 68 + r] = v.z;
        XsT[(k4 * 4 + 3) * 68 + r] = v.w;
    }
    __syncthreads();

    int tc = tid % (NC / 4), tr = tid / (NC / 4);
    int c0 = tc * 4, r0 = tr * 4;
    float acc[4][4];
    #pragma unroll
    for (int i = 0; i < 4; i++)
        #pragma unroll
        for (int j = 0; j < 4; j++) acc[i][j] = 0.f;

    #pragma unroll 8
    for (int k = 0; k < 64; k++) {
        float4 b = *(const float4*)&Ws[k * NC + c0];
        float4 a = *(const float4*)&XsT[k * 68 + r0];
        acc[0][0] += a.x * b.x; acc[0][1] += a.x * b.y; acc[0][2] += a.x * b.z; acc[0][3] += a.x * b.w;
        acc[1][0] += a.y * b.x; acc[1][1] += a.y * b.y; acc[1][2] += a.y * b.z; acc[1][3] += a.y * b.w;
        acc[2][0] += a.z * b.x; acc[2][1] += a.z * b.y; acc[2][2] += a.z * b.z; acc[2][3] += a.z * b.w;
        acc[3][0] += a.w * b.x; acc[3][1] += a.w * b.y; acc[3][2] += a.w * b.z; acc[3][3] += a.w * b.w;
    }

    #pragma unroll
    for (int i = 0; i < 4; i++) {
        int gr = row0 + r0 + i;
        if (gr < NN) {
            if (HOUT) {
                __half2 h0 = __floats2half2_rn(acc[i][0], acc[i][1]);
                __half2 h1 = __floats2half2_rn(acc[i][2], acc[i][3]);
                __half2* o2 = (__half2*)((__half*)out + (size_t)gr * 64 + c0);
                o2[0] = h0; o2[1] = h1;
            } else {
                *(float4*)&((float*)out)[(size_t)gr * NC + c0] =
                    make_float4(acc[i][0], acc[i][1], acc[i][2], acc[i][3]);
            }
        }
    }
}

// ---------------- aggregation (NC=64, fp16 h): quarter-warp uint4, 4 edges/iter ----------
// fp16 row = 128B = 8 lanes x LDG.128. Warp-quarter q handles edges st+q, st+q+4, ...
// One LDG.128 warp-instruction fetches 4 edges (4 lines). fp32 accumulate + output.
__global__ void k_agg64h(const uint4* __restrict__ h4, const float* __restrict__ bias,
                         const float* __restrict__ t, float* __restrict__ out) {
    int wid  = (blockIdx.x * blockDim.x + threadIdx.x) >> 5;
    int lane = threadIdx.x & 31;
    if (wid >= NN) return;
    int q = lane >> 3, ql = lane & 7;
    int st = g_start[wid], en = st + g_deg[wid];
    float acc[8];
    #pragma unroll
    for (int i = 0; i < 8; i++) acc[i] = 0.f;

    #pragma unroll 2
    for (int e = st + q; e < en; e += 4) {
        int2 c = __ldg(&g_cw[e]);
        uint4 v = __ldg(h4 + (size_t)c.x * 8 + ql);   // 8 halves of the row
        float w = __int_as_float(c.y);
        float2 f;
        f = __half22float2(*(const __half2*)&v.x); acc[0] += w * f.x; acc[1] += w * f.y;
        f = __half22float2(*(const __half2*)&v.y); acc[2] += w * f.x; acc[3] += w * f.y;
        f = __half22float2(*(const __half2*)&v.z); acc[4] += w * f.x; acc[5] += w * f.y;
        f = __half22float2(*(const __half2*)&v.w); acc[6] += w * f.x; acc[7] += w * f.y;
    }
    // combine the 4 quarters (same column group ql across quarters)
    #pragma unroll
    for (int i = 0; i < 8; i++) {
        acc[i] += __shfl_xor_sync(0xffffffffu, acc[i], 8);
        acc[i] += __shfl_xor_sync(0xffffffffu, acc[i], 16);
    }
    if (q == 0) {   // lanes 0-7 hold full sums for cols ql*8 .. ql*8+7
        float sd = g_s[wid];
        const float4* b4 = (const float4*)(bias + ql * 8);
        const float4* t4 = (const float4*)(t + ql * 8);
        float4 b0 = __ldg(b4), b1 = __ldg(b4 + 1);
        float4 t0 = __ldg(t4), t1 = __ldg(t4 + 1);
        float4 o0, o1;
        o0.x = acc[0] + b0.x + sd * t0.x;
        o0.y = acc[1] + b0.y + sd * t0.y;
        o0.z = acc[2] + b0.z + sd * t0.z;
        o0.w = acc[3] + b0.w + sd * t0.w;
        o1.x = acc[4] + b1.x + sd * t1.x;
        o1.y = acc[5] + b1.y + sd * t1.y;
        o1.z = acc[6] + b1.z + sd * t1.z;
        o1.w = acc[7] + b1.w + sd * t1.w;
        float4* op = (float4*)(out + (size_t)wid * 64 + ql * 8);
        op[0] = o0; op[1] = o1;
    }
}

// ---------------- aggregation (NC=40, fp32 h) + fused log_softmax ----------------
__global__ void k_agg40lsm(const float* __restrict__ h, const float* __restrict__ bias,
                           const float* __restrict__ t, float* __restrict__ emb,
                           float* __restrict__ out) {
    int wid  = (blockIdx.x * blockDim.x + threadIdx.x) >> 5;
    int lane = threadIdx.x & 31;
    if (wid >= NN) return;
    bool act = lane < 20;
    int ln = act ? lane : 0;                 // keep loads in-bounds for idle lanes
    const float2* h2 = (const float2*)h;     // row stride = 20 float2
    int e = g_start[wid], en = e + g_deg[wid];
    float ax = 0.f, ay = 0.f;
    while (e + 4 <= en) {
        int2 c0 = __ldg(&g_cw[e]);
        int2 c1 = __ldg(&g_cw[e + 1]);
        int2 c2 = __ldg(&g_cw[e + 2]);
        int2 c3 = __ldg(&g_cw[e + 3]);
        float2 v0 = __ldg(h2 + (size_t)c0.x * 20 + ln);
        float2 v1 = __ldg(h2 + (size_t)c1.x * 20 + ln);
        float2 v2 = __ldg(h2 + (size_t)c2.x * 20 + ln);
        float2 v3 = __ldg(h2 + (size_t)c3.x * 20 + ln);
        float w0 = __int_as_float(c0.y), w1 = __int_as_float(c1.y);
        float w2 = __int_as_float(c2.y), w3 = __int_as_float(c3.y);
        ax += w0 * v0.x; ay += w0 * v0.y;
        ax += w1 * v1.x; ay += w1 * v1.y;
        ax += w2 * v2.x; ay += w2 * v2.y;
        ax += w3 * v3.x; ay += w3 * v3.y;
        e += 4;
    }
    while (e < en) {
        int2 c = __ldg(&g_cw[e++]);
        float2 v = __ldg(h2 + (size_t)c.x * 20 + ln);
        float w = __int_as_float(c.y);
        ax += w * v.x; ay += w * v.y;
    }
    float sd = g_s[wid];
    float v0 = 0.f, v1 = 0.f;
    if (act) {
        int c = lane * 2;
        v0 = ax + bias[c]     + sd * t[c];
        v1 = ay + bias[c + 1] + sd * t[c + 1];
        ((float2*)emb)[(size_t)wid * 20 + lane] = make_float2(v0, v1);
    }
    float m = act ? fmaxf(v0, v1) : -3.4e38f;
    #pragma unroll
    for (int o = 16; o > 0; o >>= 1) m = fmaxf(m, __shfl_xor_sync(0xffffffffu, m, o));
    float s = act ? (__expf(v0 - m) + __expf(v1 - m)) : 0.f;
    #pragma unroll
    for (int o = 16; o > 0; o >>= 1) s += __shfl_xor_sync(0xffffffffu, s, o);
    float lse = m + logf(s);
    if (act)
        ((float2*)out)[(size_t)wid * 20 + lane] = make_float2(v0 - lse, v1 - lse);
}

// ---------------- BN column stats (sum, sumsq) ----------------
__global__ void k_stats(const float* __restrict__ a, float* __restrict__ st) {
    int col = threadIdx.x & 63, sub = threadIdx.x >> 6;
    float s = 0.f, q = 0.f;
    for (int r = blockIdx.x * 4 + sub; r < NN; r += gridDim.x * 4) {
        float v = a[(size_t)r * 64 + col];
        s += v; q += v * v;
    }
    __shared__ float shs[256], shq[256];
    shs[threadIdx.x] = s; shq[threadIdx.x] = q;
    __syncthreads();
    if (sub == 0) {
        s = shs[col] + shs[col + 64] + shs[col + 128] + shs[col + 192];
        q = shq[col] + shq[col + 64] + shq[col + 128] + shq[col + 192];
        atomicAdd(&st[col], s);
        atomicAdd(&st[col + 64], q);
    }
}

// ---------------- fold BN into next layer's weights ----------------
template <int NCN>
__global__ void k_fold(const float* __restrict__ W, const float* __restrict__ g,
                       const float* __restrict__ be, const float* __restrict__ st,
                       float* __restrict__ Wf, float* __restrict__ t) {
    __shared__ float a[64], c[64];
    int tid = threadIdx.x;
    if (tid < 64) {
        float mean = st[tid] * (1.f / NN);
        float var  = st[tid + 64] * (1.f / NN) - mean * mean;
        float ai = g[tid] * rsqrtf(var + EPSV);
        a[tid] = ai;
        c[tid] = be[tid] - mean * ai;
    }
    __syncthreads();
    for (int i = tid; i < 64 * NCN; i += 256) Wf[i] = a[i / NCN] * W[i];
    if (tid < NCN) {
        float tv = 0.f;
        #pragma unroll
        for (int k = 0; k < 64; k++) tv += c[k] * W[k * NCN + tid];
        t[tid] = tv;
    }
}

// ---------------- launcher ----------------
extern "C" void kernel_launch(void* const* d_in, const int* in_sizes, int n_in,
                              void* d_out, int out_size) {
    const float* x   = (const float*)d_in[0];
    const void*  ei  = d_in[1];                 // int32 or int64, detected on device
    const float* W1  = (const float*)d_in[2];
    const float* b1  = (const float*)d_in[3];
    const float* W2  = (const float*)d_in[4];
    const float* b2  = (const float*)d_in[5];
    const float* W3  = (const float*)d_in[6];
    const float* b3  = (const float*)d_in[7];
    const float* g1  = (const float*)d_in[8];
    const float* be1 = (const float*)d_in[9];
    const float* g2  = (const float*)d_in[10];
    const float* be2 = (const float*)d_in[11];
    float* out = (float*)d_out;

    float *hP, *aP, *W2fP, *W3fP, *t2P, *t3P, *z64P, *s1P, *s2P;
    cudaGetSymbolAddress((void**)&hP,   g_h);
    cudaGetSymbolAddress((void**)&aP,   g_agg);
    cudaGetSymbolAddress((void**)&W2fP, g_W2f);
    cudaGetSymbolAddress((void**)&W3fP, g_W3f);
    cudaGetSymbolAddress((void**)&t2P,  g_t2);
    cudaGetSymbolAddress((void**)&t3P,  g_t3);
    cudaGetSymbolAddress((void**)&z64P, g_zero64);
    cudaGetSymbolAddress((void**)&s1P,  g_stats1);
    cudaGetSymbolAddress((void**)&s2P,  g_stats2);

    // output layout: (out, emb) concatenated
    float* emb = (out_size >= 2 * NN * 40) ? (out + NN * 40) : aP;

    // graph build
    k_init  <<<(NN + 255) / 256, 256>>>((const long long*)ei);
    k_degree<<<(EE + 255) / 256, 256>>>(ei);
    k_scanA <<<NB, 256>>>();
    k_scanB <<<1, 32>>>();
    k_scanC <<<NB, 256>>>();
    k_fill  <<<(MM + 255) / 256, 256>>>(ei);

    // layer 1 (h in fp16)
    k_gemm<64, true><<<(NN + 63) / 64, 256>>>(x, W1, hP);
    k_agg64h  <<<(NN + 7) / 8, 256>>>((const uint4*)hP, b1, z64P, aP);
    k_stats   <<<256, 256>>>(aP, s1P);
    k_fold<64><<<1, 256>>>(W2, g1, be1, s1P, W2fP, t2P);

    // layer 2 (BN1 folded into W2, h in fp16)
    k_gemm<64, true><<<(NN + 63) / 64, 256>>>(aP, W2fP, hP);
    k_agg64h  <<<(NN + 7) / 8, 256>>>((const uint4*)hP, b2, t2P, aP);
    k_stats   <<<256, 256>>>(aP, s2P);
    k_fold<40><<<1, 256>>>(W3, g2, be2, s2P, W3fP, t3P);

    // layer 3 (BN2 folded into W3, fp32 throughout) -> emb + fused log_softmax -> out
    k_gemm<40, false><<<(NN + 63) / 64, 160>>>(aP, W3fP, hP);
    k_agg40lsm<<<(NN + 7) / 8, 256>>>(hP, b3, t3P, emb, out);
}